// round 2
// baseline (speedup 1.0000x reference)
#include <cuda_runtime.h>
#include <cstdint>

#define TT   512
#define NB   64
#define IN0  256
#define HID  256
#define GATES 1024
#define OC   512   // 2*HID

// ---------------- scratch (static device memory; no allocation) ----------------
__device__ float g_wi_f[(size_t)TT * NB * GATES];  // 128 MB
__device__ float g_wi_b[(size_t)TT * NB * GATES];  // 128 MB
__device__ float g_x1 [(size_t)TT * NB * OC];      // 64 MB (layer-0 output / layer-1 input)
__device__ float g_hbuf[2][2][HID * NB];           // [dir][slot][j*64 + b]
__device__ unsigned int g_ctr[2][8];               // [dir][btile] step barrier counters
__device__ int g_len[NB];                          // normalized lengths (int32)

// ---------------- lengths dtype normalization ----------------
// JAX with x64 disabled silently turns .astype(int64) into int32. Detect on
// device: if the buffer is really int64, the odd 32-bit words of the first 64
// words are the high halves of lengths < 512 -> all zero. For genuine int32
// data, 32 independent uniform[0,512) values being all zero has ~0 probability.
__global__ void prep_lengths(const int* __restrict__ lraw)
{
    __shared__ int is64;
    if (threadIdx.x == 0) {
        int allzero = 1;
        for (int i = 1; i < 64; i += 2)
            if (lraw[i] != 0) allzero = 0;
        is64 = allzero;
    }
    __syncthreads();
    int b = threadIdx.x;
    if (b < NB)
        g_len[b] = is64 ? lraw[2 * b] : lraw[b];  // little-endian low word
}

// ---------------- input GEMM: C[M=32768, N=1024] = A[M,K] @ W[K,1024] + bias ----------------
#define BM 128
#define BN 128
#define BK 16

__global__ __launch_bounds__(256, 2) void sgemm_bias(
    const float* __restrict__ A, const float* __restrict__ W,
    const float* __restrict__ bias, float* __restrict__ C, int K)
{
    __shared__ float As[BK][BM];
    __shared__ float Bs[BK][BN];
    const int bx = blockIdx.x;   // N tile (8)
    const int by = blockIdx.y;   // M tile (256)
    const int tid = threadIdx.x;
    const int tx = tid & 15;
    const int ty = tid >> 4;

    float acc[8][8];
#pragma unroll
    for (int i = 0; i < 8; i++)
#pragma unroll
        for (int j = 0; j < 8; j++) acc[i][j] = 0.f;

    const int aRow = tid >> 2;         // 0..63 (two passes -> 128 rows)
    const int aCol = (tid & 3) << 2;   // 0,4,8,12
    const int bRow = tid >> 5;         // 0..7 (two passes -> 16 rows)
    const int bCol = (tid & 31) << 2;  // 0..124

    const float* Ab = A + (size_t)(by * BM) * K;
    const float* Wb = W + bx * BN;

    for (int kb = 0; kb < K; kb += BK) {
#pragma unroll
        for (int i = 0; i < 2; i++) {
            int r = aRow + i * 64;
            float4 v = *(const float4*)(Ab + (size_t)r * K + kb + aCol);
            As[aCol + 0][r] = v.x;
            As[aCol + 1][r] = v.y;
            As[aCol + 2][r] = v.z;
            As[aCol + 3][r] = v.w;
        }
#pragma unroll
        for (int i = 0; i < 2; i++) {
            int r = bRow + i * 8;
            *(float4*)&Bs[r][bCol] = *(const float4*)(Wb + (size_t)(kb + r) * GATES + bCol);
        }
        __syncthreads();
#pragma unroll
        for (int k = 0; k < BK; k++) {
            float rm[8], rn[8];
#pragma unroll
            for (int i = 0; i < 8; i++) rm[i] = As[k][ty * 8 + i];
#pragma unroll
            for (int j = 0; j < 8; j++) rn[j] = Bs[k][tx * 8 + j];
#pragma unroll
            for (int i = 0; i < 8; i++)
#pragma unroll
                for (int j = 0; j < 8; j++) acc[i][j] = fmaf(rm[i], rn[j], acc[i][j]);
        }
        __syncthreads();
    }

    float bs[8];
#pragma unroll
    for (int j = 0; j < 8; j++) bs[j] = bias[bx * BN + tx * 8 + j];

    float* Cb = C + (size_t)(by * BM + ty * 8) * GATES + bx * BN + tx * 8;
#pragma unroll
    for (int i = 0; i < 8; i++) {
        float4 v0 = make_float4(acc[i][0] + bs[0], acc[i][1] + bs[1], acc[i][2] + bs[2], acc[i][3] + bs[3]);
        float4 v1 = make_float4(acc[i][4] + bs[4], acc[i][5] + bs[5], acc[i][6] + bs[6], acc[i][7] + bs[7]);
        *(float4*)(Cb + (size_t)i * GATES + 0) = v0;
        *(float4*)(Cb + (size_t)i * GATES + 4) = v1;
    }
}

// ---------------- reset h-exchange buffers + barrier counters ----------------
__global__ void init_state()
{
    int i = blockIdx.x * blockDim.x + threadIdx.x;
    if (i < 2 * 2 * HID * NB) ((float*)g_hbuf)[i] = 0.f;
    if (i < 16) ((unsigned int*)g_ctr)[i] = 0u;
}

// ---------------- recurrent kernel (one layer, both directions) ----------------
// grid = 128 CTAs: dir(2) x btile(8, 8 batch each) x ci(8, 32 h-cols each)
// Each CTA: weights slice (256 x 128 gate-cols) resident in smem for all 512 steps.
// h exchanged via g_hbuf (L2, double-buffered by step parity), 8-CTA barrier per (dir,btile).

__device__ __forceinline__ float sigm(float x) { return 1.f / (1.f + expf(-x)); }

__global__ __launch_bounds__(128) void lstm_layer(
    const float* __restrict__ wi_f, const float* __restrict__ wi_b,
    const float* __restrict__ Whh_f, const float* __restrict__ Whh_b,
    float* __restrict__ outbuf,        // [TT][NB][OC]
    float* __restrict__ hn, float* __restrict__ cn)  // [2][NB][HID] (this layer)
{
    extern __shared__ float smem[];
    float* sW = smem;                 // 256*128 floats (128 KB), [k][col]
    float* sH = smem + 256 * 128;     // 256*8 floats, [k][b]
    float* sG = sH + 256 * 8;         // 4*8*32 floats gate staging

    const int dir   = blockIdx.x >> 6;
    const int rem   = blockIdx.x & 63;
    const int btile = rem >> 3;
    const int ci    = rem & 7;
    const int b0    = btile << 3;
    const int tid   = threadIdx.x;
    const int gate  = tid >> 5;
    const int jj    = tid & 31;
    const int jglob = (ci << 5) + jj;
    const int gcol  = (gate << 8) + jglob;

    const float* wi  = dir ? wi_b  : wi_f;
    const float* Whh = dir ? Whh_b : Whh_f;

    // load resident weight slice (once)
#pragma unroll 4
    for (int k = 0; k < 256; k++)
        sW[k * 128 + tid] = __ldg(Whh + (size_t)k * GATES + gcol);

    // cell-state ownership: thread owns cells (jj, bA) and (jj, bB)
    const int bA = (tid >> 5) << 1;
    const int bB = bA + 1;
    const int lenA = g_len[b0 + bA];
    const int lenB = g_len[b0 + bB];
    float cA = 0.f, cB = 0.f, hA = 0.f, hB = 0.f;

    volatile unsigned int* ctrv = &g_ctr[dir][btile];
    __syncthreads();

    for (int s = 0; s < TT; s++) {
        // gather h tile (written by all 8 CTAs of this (dir,btile) last step) -> smem
        const float* hb = g_hbuf[dir][s & 1];
#pragma unroll
        for (int i = 0; i < 16; i++) {
            int idx = tid + (i << 7);
            sH[idx] = __ldcg(hb + ((idx >> 3) << 6) + b0 + (idx & 7));
        }
        const int t = dir ? (TT - 1 - s) : s;

        // prefetch wi for this step (hidden under the k-loop)
        const float* wrow = wi + ((size_t)t * NB + b0) * GATES + gcol;
        float a0 = __ldg(wrow + 0 * GATES);
        float a1 = __ldg(wrow + 1 * GATES);
        float a2 = __ldg(wrow + 2 * GATES);
        float a3 = __ldg(wrow + 3 * GATES);
        float a4 = __ldg(wrow + 4 * GATES);
        float a5 = __ldg(wrow + 5 * GATES);
        float a6 = __ldg(wrow + 6 * GATES);
        float a7 = __ldg(wrow + 7 * GATES);
        __syncthreads();

#pragma unroll 8
        for (int k = 0; k < 256; k++) {
            float w  = sW[k * 128 + tid];
            float4 h0 = *(const float4*)(sH + (k << 3));
            float4 h1 = *(const float4*)(sH + (k << 3) + 4);
            a0 = fmaf(w, h0.x, a0);
            a1 = fmaf(w, h0.y, a1);
            a2 = fmaf(w, h0.z, a2);
            a3 = fmaf(w, h0.w, a3);
            a4 = fmaf(w, h1.x, a4);
            a5 = fmaf(w, h1.y, a5);
            a6 = fmaf(w, h1.z, a6);
            a7 = fmaf(w, h1.w, a7);
        }

        // stage gate pre-activations: sG[gate*256 + b*32 + jj]
        {
            float* gg = sG + (gate << 8) + jj;
            gg[0]   = a0; gg[32]  = a1; gg[64]  = a2; gg[96]  = a3;
            gg[128] = a4; gg[160] = a5; gg[192] = a6; gg[224] = a7;
        }
        __syncthreads();

        // cell updates (each thread owns 2 cells, state in registers)
        {
            int iA = (bA << 5) + jj;
            float gi = sG[iA], gf = sG[256 + iA], go = sG[512 + iA], gc = sG[768 + iA];
            float cN = sigm(gf + 1.f) * cA + sigm(gi) * tanhf(gc);
            float hN = sigm(go) * tanhf(cN);
            float ov = 0.f;
            if (t < lenA) { cA = cN; hA = hN; ov = hN; }
            outbuf[((size_t)s * NB + b0 + bA) * OC + (dir << 8) + jglob] = ov;
            __stcg(&g_hbuf[dir][(s + 1) & 1][(jglob << 6) + b0 + bA], hA);
        }
        {
            int iB = (bB << 5) + jj;
            float gi = sG[iB], gf = sG[256 + iB], go = sG[512 + iB], gc = sG[768 + iB];
            float cN = sigm(gf + 1.f) * cB + sigm(gi) * tanhf(gc);
            float hN = sigm(go) * tanhf(cN);
            float ov = 0.f;
            if (t < lenB) { cB = cN; hB = hN; ov = hN; }
            outbuf[((size_t)s * NB + b0 + bB) * OC + (dir << 8) + jglob] = ov;
            __stcg(&g_hbuf[dir][(s + 1) & 1][(jglob << 6) + b0 + bB], hB);
        }

        __threadfence();
        __syncthreads();
        if (tid == 0) {
            atomicAdd(&g_ctr[dir][btile], 1u);
            unsigned int target = (unsigned int)((s + 1) << 3);
            while (*ctrv < target) __nanosleep(64);
        }
        __syncthreads();
        __threadfence();   // acquire: order hbuf reads of next step after the spin
    }

    // final states (held through masking, like the reference carry)
    hn[((size_t)dir * NB + b0 + bA) * HID + jglob] = hA;
    hn[((size_t)dir * NB + b0 + bB) * HID + jglob] = hB;
    cn[((size_t)dir * NB + b0 + bA) * HID + jglob] = cA;
    cn[((size_t)dir * NB + b0 + bB) * HID + jglob] = cB;
}

// ---------------- launcher ----------------
extern "C" void kernel_launch(void* const* d_in, const int* in_sizes, int n_in,
                              void* d_out, int out_size)
{
    const float* inputs  = (const float*)d_in[0];
    const int*   lengths = (const int*)d_in[1];   // width auto-detected on device
    const float* Wih_f0 = (const float*)d_in[2];
    const float* Whh_f0 = (const float*)d_in[3];
    const float* b_f0   = (const float*)d_in[4];
    const float* Wih_b0 = (const float*)d_in[5];
    const float* Whh_b0 = (const float*)d_in[6];
    const float* b_b0   = (const float*)d_in[7];
    const float* Wih_f1 = (const float*)d_in[8];
    const float* Whh_f1 = (const float*)d_in[9];
    const float* b_f1   = (const float*)d_in[10];
    const float* Wih_b1 = (const float*)d_in[11];
    const float* Whh_b1 = (const float*)d_in[12];
    const float* b_b1   = (const float*)d_in[13];
    float* out = (float*)d_out;

    float *wi_f, *wi_b, *x1;
    cudaGetSymbolAddress((void**)&wi_f, g_wi_f);
    cudaGetSymbolAddress((void**)&wi_b, g_wi_b);
    cudaGetSymbolAddress((void**)&x1,  g_x1);

    const int smemRec = (256 * 128 + 256 * 8 + 1024) * (int)sizeof(float);  // ~140 KB
    cudaFuncSetAttribute(lstm_layer, cudaFuncAttributeMaxDynamicSharedMemorySize, smemRec);

    float* hn0 = out + (size_t)TT * NB * OC;          // hn: (4, B, H)
    float* cn0 = hn0 + 4 * NB * HID;                  // cn: (4, B, H)

    dim3 gGrid(8, 256);

    prep_lengths<<<1, 64>>>(lengths);

    // layer 0
    sgemm_bias<<<gGrid, 256>>>(inputs, Wih_f0, b_f0, wi_f, IN0);
    sgemm_bias<<<gGrid, 256>>>(inputs, Wih_b0, b_b0, wi_b, IN0);
    init_state<<<256, 256>>>();
    lstm_layer<<<128, 128, smemRec>>>(wi_f, wi_b, Whh_f0, Whh_b0, x1, hn0, cn0);

    // layer 1
    sgemm_bias<<<gGrid, 256>>>(x1, Wih_f1, b_f1, wi_f, OC);
    sgemm_bias<<<gGrid, 256>>>(x1, Wih_b1, b_b1, wi_b, OC);
    init_state<<<256, 256>>>();
    lstm_layer<<<128, 128, smemRec>>>(wi_f, wi_b, Whh_f1, Whh_b1, out,
                                      hn0 + 2 * NB * HID, cn0 + 2 * NB * HID);
}